// round 14
// baseline (speedup 1.0000x reference)
#include <cuda_runtime.h>
#include <cuda_bf16.h>

#define NB 16
#define NC 256
#define NS 4096
#define NH 512
#define NHEADS 8
#define KSPLIT 4

typedef unsigned long long u64;
typedef unsigned int u32;
typedef unsigned short u16;

// ---------------- scratch (static device memory, 16B-aligned) ----------------
__device__ __align__(16) float g_Gpart[KSPLIT][NB][NC][NC];  // 16 MB
__device__ __align__(16) float g_QG[NB][NH][NC];             // 8 MB
__device__ __align__(16) __nv_bfloat16 g_Ghi[NB][NC][NC];    // 2 MB
__device__ __align__(16) __nv_bfloat16 g_Glo[NB][NC][NC];    // 2 MB
__device__ __align__(16) __nv_bfloat16 g_Mhi[NB][NH][NC];    // 4 MB
__device__ __align__(16) __nv_bfloat16 g_Mlo[NB][NH][NC];    // 4 MB
__device__ __align__(16) __nv_bfloat16 g_Phi[NB][NC][NC];    // 2 MB
__device__ __align__(16) __nv_bfloat16 g_Plo[NB][NC][NC];    // 2 MB
__device__ __align__(16) __nv_bfloat16 g_Xhi[NB][NC][NS];    // 32 MB
__device__ __align__(16) __nv_bfloat16 g_Xlo[NB][NC][NS];    // 32 MB
__device__ __align__(16) __nv_bfloat16 g_Wqhi[NH * NC], g_Wqlo[NH * NC];
__device__ __align__(16) __nv_bfloat16 g_Wouthi[NC * NH], g_Woutlo[NC * NH];

// ---------------- helpers ----------------------------------------------------
__device__ __forceinline__ u32 smem_u32(const void* p) {
    u32 a;
    asm("{ .reg .u64 t; cvta.to.shared.u64 t, %1; cvt.u32.u64 %0, t; }" : "=r"(a) : "l"(p));
    return a;
}
__device__ __forceinline__ void split4(float4 v, u64& hv, u64& lv) {
    __nv_bfloat16 h0 = __float2bfloat16(v.x), h1 = __float2bfloat16(v.y);
    __nv_bfloat16 h2 = __float2bfloat16(v.z), h3 = __float2bfloat16(v.w);
    __nv_bfloat16 l0 = __float2bfloat16(v.x - __bfloat162float(h0));
    __nv_bfloat16 l1 = __float2bfloat16(v.y - __bfloat162float(h1));
    __nv_bfloat16 l2 = __float2bfloat16(v.z - __bfloat162float(h2));
    __nv_bfloat16 l3 = __float2bfloat16(v.w - __bfloat162float(h3));
    hv = (u64)__bfloat16_as_ushort(h0) | ((u64)__bfloat16_as_ushort(h1) << 16) |
         ((u64)__bfloat16_as_ushort(h2) << 32) | ((u64)__bfloat16_as_ushort(h3) << 48);
    lv = (u64)__bfloat16_as_ushort(l0) | ((u64)__bfloat16_as_ushort(l1) << 16) |
         ((u64)__bfloat16_as_ushort(l2) << 32) | ((u64)__bfloat16_as_ushort(l3) << 48);
}
__device__ __forceinline__ void split1(float v, __nv_bfloat16& h, __nv_bfloat16& l) {
    h = __float2bfloat16(v);
    l = __float2bfloat16(v - __bfloat162float(h));
}
__device__ __forceinline__ void split2_u32(float a, float b, u32& hw, u32& lw) {
    __nv_bfloat16 ha, la, hb, lb;
    split1(a, ha, la);
    split1(b, hb, lb);
    hw = (u32)__bfloat16_as_ushort(ha) | ((u32)__bfloat16_as_ushort(hb) << 16);
    lw = (u32)__bfloat16_as_ushort(la) | ((u32)__bfloat16_as_ushort(lb) << 16);
}
__device__ __forceinline__ void ldsm4(u32* r, u32 addr) {
    asm volatile("ldmatrix.sync.aligned.m8n8.x4.shared.b16 {%0,%1,%2,%3}, [%4];"
                 : "=r"(r[0]), "=r"(r[1]), "=r"(r[2]), "=r"(r[3]) : "r"(addr));
}
__device__ __forceinline__ void ldsm4t(u32* r, u32 addr) {
    asm volatile("ldmatrix.sync.aligned.m8n8.x4.trans.shared.b16 {%0,%1,%2,%3}, [%4];"
                 : "=r"(r[0]), "=r"(r[1]), "=r"(r[2]), "=r"(r[3]) : "r"(addr));
}
__device__ __forceinline__ void mma_bf16(float* d, const u32* a, const u32* b) {
    asm volatile("mma.sync.aligned.m16n8k16.row.col.f32.bf16.bf16.f32 "
        "{%0,%1,%2,%3}, {%4,%5,%6,%7}, {%8,%9}, {%0,%1,%2,%3};"
        : "+f"(d[0]), "+f"(d[1]), "+f"(d[2]), "+f"(d[3])
        : "r"(a[0]), "r"(a[1]), "r"(a[2]), "r"(a[3]), "r"(b[0]), "r"(b[1]));
}
#define CP16(dst, src) asm volatile("cp.async.cg.shared.global [%0], [%1], 16;" :: "r"(dst), "l"(src))
#define CP_COMMIT()    asm volatile("cp.async.commit_group;" ::: "memory")
#define CP_WAIT1()     asm volatile("cp.async.wait_group 1;" ::: "memory")
#define CP_WAIT0()     asm volatile("cp.async.wait_group 0;" ::: "memory")

#define LDW 72
#define LDWB 136
#define TA 18432
#define TTB 17408
#define STG_A (4 * TA)
#define STG_T (2 * TA + 2 * TTB)
#define PIPE_A (2 * STG_A)
#define PIPE_T (2 * STG_T)
#define NT 512

// shared mma stage: A nontrans always; B nontrans (TB=0) or trans (TB=1)
template <bool TB>
__device__ __forceinline__ void mma_stage(u32 aHb, u32 aLb, u32 bHb, u32 bLb,
                                          int offA, int offBx, int wm, int wn,
                                          float acc[2][4][4]) {
#pragma unroll
    for (int ks = 0; ks < 4; ks++) {
        u32 ah[2][4], al[2][4], bh[2][4], bl[2][4];
#pragma unroll
        for (int mf = 0; mf < 2; mf++) {
            u32 o = 2u * (u32)(offA + (wm * 32 + mf * 16) * LDW + ks * 16);
            ldsm4(ah[mf], aHb + o);
            ldsm4(al[mf], aLb + o);
        }
#pragma unroll
        for (int p = 0; p < 2; p++) {
            if (TB) {
                u32 o = 2u * (u32)(offBx + ks * 16 * LDWB + wn * 32 + p * 16);
                ldsm4t(bh[p], bHb + o);
                ldsm4t(bl[p], bLb + o);
            } else {
                u32 o = 2u * (u32)(offBx + (wn * 32 + p * 16) * LDW + ks * 16);
                ldsm4(bh[p], bHb + o);
                ldsm4(bl[p], bLb + o);
            }
        }
#pragma unroll
        for (int mf = 0; mf < 2; mf++)
#pragma unroll
            for (int p = 0; p < 2; p++)
#pragma unroll
                for (int hh = 0; hh < 2; hh++) {
                    int nb = p * 2 + hh;
                    mma_bf16(acc[mf][nb], ah[mf], &bh[p][hh * 2]);
                    mma_bf16(acc[mf][nb], ah[mf], &bl[p][hh * 2]);
                    mma_bf16(acc[mf][nb], al[mf], &bh[p][hh * 2]);
                }
    }
}

// =============================================================================
// convert_x: X fp32 -> Xhi/Xlo bf16 [b][c][ns]. grid 8192 x 256.
// =============================================================================
__global__ __launch_bounds__(256) void convert_x(const float* __restrict__ x) {
    size_t i = ((size_t)blockIdx.x * 256 + threadIdx.x) * 8;
    float4 v0 = *(const float4*)(x + i);
    float4 v1 = *(const float4*)(x + i + 4);
    u64 h0, l0, h1, l1;
    split4(v0, h0, l0);
    split4(v1, h1, l1);
    *(ulonglong2*)((__nv_bfloat16*)g_Xhi + i) = make_ulonglong2(h0, h1);
    *(ulonglong2*)((__nv_bfloat16*)g_Xlo + i) = make_ulonglong2(l0, l1);
}

// =============================================================================
// convert_w: Wq + W_out -> split bf16. grid 128 x 256.
// =============================================================================
__global__ __launch_bounds__(256) void convert_w(const float* __restrict__ wq,
                                                 const float* __restrict__ wo) {
    int i = (blockIdx.x * 256 + threadIdx.x) * 8;
    const int NQ = NH * NC;
    const float* src;
    __nv_bfloat16 *dh, *dl;
    if (i < NQ) { src = wq + i; dh = g_Wqhi + i; dl = g_Wqlo + i; }
    else { int o = i - NQ; src = wo + o; dh = g_Wouthi + o; dl = g_Woutlo + o; }
    float4 v0 = *(const float4*)src;
    float4 v1 = *(const float4*)(src + 4);
    u64 h0, l0, h1, l1;
    split4(v0, h0, l0);
    split4(v1, h1, l1);
    *(ulonglong2*)dh = make_ulonglong2(h0, h1);
    *(ulonglong2*)dl = make_ulonglong2(l0, l1);
}

// =============================================================================
// gram_mma: symmetric blocks ((0,0),(0,1),(1,1)) x k-quarters.
// grid (3, KSPLIT, NB), 512 thr.
// =============================================================================
__global__ __launch_bounds__(NT) void gram_mma() {
    extern __shared__ __align__(16) char sm[];
    const u32 smb = smem_u32(sm);

    const int bx = blockIdx.x;
    const int bi = (bx == 2) ? 1 : 0;
    const int bj = (bx == 0) ? 0 : 1;
    const int s = blockIdx.y, b = blockIdx.z;
    const int tid = threadIdx.x, lane = tid & 31, wid = tid >> 5;
    const int wm = wid >> 2, wn = wid & 3;
    const bool diag = (bi == bj);

    const int g = lane >> 3, r8 = lane & 7;
    const int offA = (r8 + (g & 1) * 8) * LDW + (g >> 1) * 8;
    const int offB = (r8 + (g >> 1) * 8) * LDW + (g & 1) * 8;

    const int fr = tid >> 2, fs = (tid & 3) * 32;

    float acc[2][4][4] = {};
    const int NCH = NS / KSPLIT / 64;   // 16

#define GRAM_FILL(st, c) do {                                                       \
    const int _k0 = s * (NS / KSPLIT) + (c) * 64;                                   \
    const u32 _sb = smb + (st) * STG_A;                                             \
    const char* _ah = (const char*)&g_Xhi[b][bi * 128 + fr][_k0] + fs;              \
    const char* _al = (const char*)&g_Xlo[b][bi * 128 + fr][_k0] + fs;              \
    u32 _dA = _sb + fr * 144 + fs;                                                  \
    CP16(_dA, _ah); CP16(_dA + 16, _ah + 16);                                       \
    CP16(_dA + TA, _al); CP16(_dA + TA + 16, _al + 16);                             \
    if (!diag) {                                                                    \
        const char* _bh = (const char*)&g_Xhi[b][bj * 128 + fr][_k0] + fs;          \
        const char* _bl = (const char*)&g_Xlo[b][bj * 128 + fr][_k0] + fs;          \
        u32 _dB = _sb + 2 * TA + fr * 144 + fs;                                     \
        CP16(_dB, _bh); CP16(_dB + 16, _bh + 16);                                   \
        CP16(_dB + TA, _bl); CP16(_dB + TA + 16, _bl + 16);                         \
    }                                                                               \
    CP_COMMIT();                                                                    \
} while (0)

    GRAM_FILL(0, 0);
    for (int c = 0; c < NCH; c++) {
        const int st = c & 1;
        if (c + 1 < NCH) { GRAM_FILL(st ^ 1, c + 1); CP_WAIT1(); }
        else CP_WAIT0();
        __syncthreads();
        const u32 aHb = smb + st * STG_A;
        const u32 aLb = aHb + TA;
        const u32 bHb = diag ? aHb : aHb + 2 * TA;
        const u32 bLb = diag ? aLb : aHb + 3 * TA;
        mma_stage<false>(aHb, aLb, bHb, bLb, offA, offB, wm, wn, acc);
        __syncthreads();
    }

    float* Gp = &g_Gpart[s][b][0][0];
    const int re = bi * 128 + wm * 32 + (lane >> 2);
    const int ce = bj * 128 + wn * 32 + 2 * (lane & 3);
#pragma unroll
    for (int mf = 0; mf < 2; mf++)
#pragma unroll
        for (int nb = 0; nb < 4; nb++) {
            int rr = re + mf * 16, cc = ce + nb * 8;
            float2 v0; v0.x = acc[mf][nb][0]; v0.y = acc[mf][nb][1];
            float2 v1; v1.x = acc[mf][nb][2]; v1.y = acc[mf][nb][3];
            *(float2*)&Gp[(size_t)rr * NC + cc] = v0;
            *(float2*)&Gp[(size_t)(rr + 8) * NC + cc] = v1;
        }
}

// =============================================================================
// reduce_split_g: G = sum_s Gpart[s], mirror block (1,0) from (0,1), split out.
// grid (16, NB), 256 thr.
// =============================================================================
__global__ __launch_bounds__(256) void reduce_split_g() {
    const int t = blockIdx.x, b = blockIdx.y;
    const int ti = t >> 2, tj = t & 3;
    const int tid = threadIdx.x;
    const int r = tid >> 2, j = tid & 3;
    const bool mirror = (ti >= 2 && tj < 2);
    const size_t ps = (size_t)NB * NC * NC;
    const float* P0 = &g_Gpart[0][b][0][0];

    if (!mirror) {
        int gr = ti * 64 + r, gc = tj * 64 + j * 16;
        u32 hw[8], lw[8];
#pragma unroll
        for (int q = 0; q < 4; q++) {
            float4 a = *(const float4*)(P0 + (size_t)gr * NC + gc + q * 4);
#pragma unroll
            for (int sp = 1; sp < KSPLIT; sp++) {
                float4 c = *(const float4*)(P0 + sp * ps + (size_t)gr * NC + gc + q * 4);
                a.x += c.x; a.y += c.y; a.z += c.z; a.w += c.w;
            }
            split2_u32(a.x, a.y, hw[2 * q], lw[2 * q]);
            split2_u32(a.z, a.w, hw[2 * q + 1], lw[2 * q + 1]);
        }
        uint4* dh = (uint4*)&g_Ghi[b][gr][gc];
        uint4* dl = (uint4*)&g_Glo[b][gr][gc];
        dh[0] = make_uint4(hw[0], hw[1], hw[2], hw[3]);
        dh[1] = make_uint4(hw[4], hw[5], hw[6], hw[7]);
        dl[0] = make_uint4(lw[0], lw[1], lw[2], lw[3]);
        dl[1] = make_uint4(lw[4], lw[5], lw[6], lw[7]);
    } else {
        __shared__ __align__(16) float T[64][68];
        int sr = tj * 64 + r, sc = ti * 64 + j * 16;
#pragma unroll
        for (int q = 0; q < 4; q++) {
            float4 a = *(const float4*)(P0 + (size_t)sr * NC + sc + q * 4);
#pragma unroll
            for (int sp = 1; sp < KSPLIT; sp++) {
                float4 c = *(const float4*)(P0 + sp * ps + (size_t)sr * NC + sc + q * 4);
                a.x += c.x; a.y += c.y; a.z += c.z; a.w += c.w;
            }
            *(float4*)&T[r][j * 16 + q * 4] = a;
        }
        __syncthreads();
        u32 hw[8], lw[8];
#pragma unroll
        for (int kk = 0; kk < 8; kk++)
            split2_u32(T[j * 16 + 2 * kk][r], T[j * 16 + 2 * kk + 1][r], hw[kk], lw[kk]);
        uint4* dh = (uint4*)&g_Ghi[b][ti * 64 + r][tj * 64 + j * 16];
        uint4* dl = (uint4*)&g_Glo[b][ti * 64 + r][tj * 64 + j * 16];
        dh[0] = make_uint4(hw[0], hw[1], hw[2], hw[3]);
        dh[1] = make_uint4(hw[4], hw[5], hw[6], hw[7]);
        dl[0] = make_uint4(lw[0], lw[1], lw[2], lw[3]);
        dl[1] = make_uint4(lw[4], lw[5], lw[6], lw[7]);
    }
}

// =============================================================================
// gemm_tc0: QG = Wq*G (K=256), all-copy fills, pipelined. grid (2,4,NB).
// =============================================================================
__global__ __launch_bounds__(NT) void gemm_tc0() {
    extern __shared__ __align__(16) char sm[];
    const u32 smb = smem_u32(sm);
    const int nt = blockIdx.x, mt = blockIdx.y, b = blockIdx.z;
    const int tid = threadIdx.x, lane = tid & 31, wid = tid >> 5;
    const int wm = wid >> 2, wn = wid & 3;
    const int g = lane >> 3, r8 = lane & 7;
    const int offA = (r8 + (g & 1) * 8) * LDW + (g >> 1) * 8;
    const int offB = (r8 + (g >> 1) * 8) * LDW + (g & 1) * 8;
    const int fr = tid >> 2, fs = (tid & 3) * 32;

    float acc[2][4][4] = {};
    const int NCH = 4;

#define TC0_FILL(st, c) do {                                                        \
    const int _k0 = (c) * 64;                                                       \
    const u32 _sb = smb + (st) * STG_A;                                             \
    const char* _ah = (const char*)(g_Wqhi + (size_t)(mt * 128 + fr) * NC + _k0) + fs; \
    const char* _al = (const char*)(g_Wqlo + (size_t)(mt * 128 + fr) * NC + _k0) + fs; \
    u32 _dA = _sb + fr * 144 + fs;                                                  \
    CP16(_dA, _ah); CP16(_dA + 16, _ah + 16);                                       \
    CP16(_dA + TA, _al); CP16(_dA + TA + 16, _al + 16);                             \
    const char* _bh = (const char*)&g_Ghi[b][nt * 128 + fr][_k0] + fs;              \
    const char* _bl = (const char*)&g_Glo[b][nt * 128 + fr][_k0] + fs;              \
    u32 _dB = _sb + 2 * TA + fr * 144 + fs;                                         \
    CP16(_dB, _bh); CP16(_dB + 16, _bh + 16);                                       \
    CP16(_dB + TA, _bl); CP16(_dB + TA + 16, _bl + 16);                             \
    CP_COMMIT();                                                                    \
} while (0)

    TC0_FILL(0, 0);
    for (int c = 0; c < NCH; c++) {
        const int st = c & 1;
        if (c + 1 < NCH) { TC0_FILL(st ^ 1, c + 1); CP_WAIT1(); }
        else CP_WAIT0();
        __syncthreads();
        const u32 aHb = smb + st * STG_A;
        mma_stage<false>(aHb, aHb + TA, aHb + 2 * TA, aHb + 3 * TA, offA, offB, wm, wn, acc);
        __syncthreads();
    }

    float* Cb = &g_QG[b][0][0];
    const int mB = mt * 128 + wm * 32 + (lane >> 2);
    const int nB = nt * 128 + wn * 32 + 2 * (lane & 3);
#pragma unroll
    for (int mf = 0; mf < 2; mf++) {
        int r = mB + mf * 16;
#pragma unroll
        for (int nb = 0; nb < 4; nb++) {
            int cc = nB + nb * 8;
            float2 v0; v0.x = acc[mf][nb][0]; v0.y = acc[mf][nb][1];
            float2 v1; v1.x = acc[mf][nb][2]; v1.y = acc[mf][nb][3];
            *(float2*)&Cb[(size_t)r * NC + cc] = v0;
            *(float2*)&Cb[(size_t)(r + 8) * NC + cc] = v1;
        }
    }
}

// =============================================================================
// gemm_tc1: P = W_out*M (K=512), B via trans, pipelined. grid (2,2,NB).
// =============================================================================
__global__ __launch_bounds__(NT) void gemm_tc1() {
    extern __shared__ __align__(16) char sm[];
    const u32 smb = smem_u32(sm);
    const int nt = blockIdx.x, mt = blockIdx.y, b = blockIdx.z;
    const int tid = threadIdx.x, lane = tid & 31, wid = tid >> 5;
    const int wm = wid >> 2, wn = wid & 3;
    const int g = lane >> 3, r8 = lane & 7;
    const int offA = (r8 + (g & 1) * 8) * LDW + (g >> 1) * 8;
    const int offBT = (r8 + (g & 1) * 8) * LDWB + (g >> 1) * 8;
    const int fr = tid >> 2, fs = (tid & 3) * 32;
    const int r2 = tid >> 3, f2 = (tid & 7) * 32;

    float acc[2][4][4] = {};
    const int NCH = 8;

#define TC1_FILL(st, c) do {                                                        \
    const int _k0 = (c) * 64;                                                       \
    const u32 _sb = smb + (st) * STG_T;                                             \
    const char* _ah = (const char*)(g_Wouthi + (size_t)(mt * 128 + fr) * NH + _k0) + fs; \
    const char* _al = (const char*)(g_Woutlo + (size_t)(mt * 128 + fr) * NH + _k0) + fs; \
    u32 _dA = _sb + fr * 144 + fs;                                                  \
    CP16(_dA, _ah); CP16(_dA + 16, _ah + 16);                                       \
    CP16(_dA + TA, _al); CP16(_dA + TA + 16, _al + 16);                             \
    const char* _bh = (const char*)&g_Mhi[b][_k0 + r2][nt * 128] + f2;              \
    const char* _bl = (const char*)&g_Mlo[b][_k0 + r2][nt * 128] + f2;              \
    u32 _dB = _sb + 2 * TA + r2 * 272 + f2;                                         \
    CP16(_dB, _bh); CP16(_dB + 16, _bh + 16);                                       \
    CP16(_dB + TTB, _bl); CP16(_dB + TTB + 16, _bl + 16);                           \
    CP_COMMIT();                                                                    \
} while (0)

    TC1_FILL(0, 0);
    for (int c = 0; c < NCH; c++) {
        const int st = c & 1;
        if (c + 1 < NCH) { TC1_FILL(st ^ 1, c + 1); CP_WAIT1(); }
        else CP_WAIT0();
        __syncthreads();
        const u32 aHb = smb + st * STG_T;
        mma_stage<true>(aHb, aHb + TA, aHb + 2 * TA, aHb + 2 * TA + TTB, offA, offBT, wm, wn, acc);
        __syncthreads();
    }

    const int mB = mt * 128 + wm * 32 + (lane >> 2);
    const int nB = nt * 128 + wn * 32 + 2 * (lane & 3);
#pragma unroll
    for (int mf = 0; mf < 2; mf++) {
        int r = mB + mf * 16;
#pragma unroll
        for (int nb = 0; nb < 4; nb++) {
            int cc = nB + nb * 8;
            u32 hw, lw;
            split2_u32(acc[mf][nb][0], acc[mf][nb][1], hw, lw);
            *(u32*)&g_Phi[b][r][cc] = hw;
            *(u32*)&g_Plo[b][r][cc] = lw;
            split2_u32(acc[mf][nb][2], acc[mf][nb][3], hw, lw);
            *(u32*)&g_Phi[b][r + 8][cc] = hw;
            *(u32*)&g_Plo[b][r + 8][cc] = lw;
        }
    }
}

// =============================================================================
// attn: sim -> softmax -> M quarter = attn*Wv[:, q*64:(q+1)*64].
// grid (NHEADS, 4, NB), 256 thr. sim+softmax duplicated per quarter (cheap).
// =============================================================================
__global__ __launch_bounds__(256) void attn_kernel(const float* __restrict__ wqkv) {
    const int h = blockIdx.x, quarter = blockIdx.y, b = blockIdx.z;
    __shared__ float S[64][65];
    __shared__ __align__(16) float Buf[4160];
    const int tid = threadIdx.x, tx = tid & 15, ty = tid >> 4;

    const float* QGb = &g_QG[b][h * 64][0];
    const float* Wk = wqkv + (size_t)(NH + h * 64) * NC;
    const float* Wv = wqkv + (size_t)(2 * NH + h * 64) * NC;
    float* Qs = Buf;
    float* Ks = Buf + 64 * 32;

    float acc[4][4] = {};
    for (int kc = 0; kc < NC; kc += 32) {
#pragma unroll
        for (int it = 0; it < 2; it++) {
            int idx = it * 256 + tid;
            int row = idx >> 3, c4 = idx & 7;
            *(float4*)&Qs[row * 32 + c4 * 4] = *(const float4*)(QGb + (size_t)row * NC + kc + c4 * 4);
            float4 v = *(const float4*)(Wk + (size_t)row * NC + kc + c4 * 4);
            Ks[(c4 * 4 + 0) * 65 + row] = v.x;
            Ks[(c4 * 4 + 1) * 65 + row] = v.y;
            Ks[(c4 * 4 + 2) * 65 + row] = v.z;
            Ks[(c4 * 4 + 3) * 65 + row] = v.w;
        }
        __syncthreads();
#pragma unroll
        for (int kk = 0; kk < 32; kk++) {
            float a[4], bb[4];
#pragma unroll
            for (int i = 0; i < 4; i++) a[i] = Qs[(ty + 16 * i) * 32 + kk];
#pragma unroll
            for (int j = 0; j < 4; j++) bb[j] = Ks[kk * 65 + tx + 16 * j];
#pragma unroll
            for (int i = 0; i < 4; i++)
#pragma unroll
                for (int j = 0; j < 4; j++) acc[i][j] += a[i] * bb[j];
        }
        __syncthreads();
    }
    const float scale = 0.125f;
#pragma unroll
    for (int i = 0; i < 4; i++)
#pragma unroll
        for (int j = 0; j < 4; j++)
            S[ty + 16 * i][tx + 16 * j] = acc[i][j] * scale;
    __syncthreads();

    if (tid < 64) {
        float m = -1e30f;
        for (int j = 0; j < 64; j++) m = fmaxf(m, S[tid][j]);
        float sum = 0.f;
        for (int j = 0; j < 64; j++) {
            float e = expf(S[tid][j] - m);
            S[tid][j] = e; sum += e;
        }
        float inv = 1.f / sum;
        for (int j = 0; j < 64; j++) S[tid][j] *= inv;
    }
    __syncthreads();

    float* Vs = Buf;
    const int cc = quarter * 64;
    {
#pragma unroll
        for (int it = 0; it < 4; it++) {
            int idx = it * 256 + tid;
            int row = idx >> 4, c4 = idx & 15;
            *(float4*)&Vs[row * 64 + c4 * 4] = *(const float4*)(Wv + (size_t)row * NC + cc + c4 * 4);
        }
        __syncthreads();
        float o[4][4] = {};
        for (int j = 0; j < 64; j++) {
            float a[4], vv[4];
#pragma unroll
            for (int i = 0; i < 4; i++) a[i] = S[ty + 16 * i][j];
#pragma unroll
            for (int jj = 0; jj < 4; jj++) vv[jj] = Vs[j * 64 + tx + 16 * jj];
#pragma unroll
            for (int i = 0; i < 4; i++)
#pragma unroll
                for (int jj = 0; jj < 4; jj++) o[i][jj] += a[i] * vv[jj];
        }
#pragma unroll
        for (int i = 0; i < 4; i++)
#pragma unroll
            for (int jj = 0; jj < 4; jj++) {
                __nv_bfloat16 hv, lv;
                split1(o[i][jj], hv, lv);
                int hd = h * 64 + ty + 16 * i, ccol = cc + tx + 16 * jj;
                g_Mhi[b][hd][ccol] = hv;
                g_Mlo[b][hd][ccol] = lv;
            }
    }
}

// =============================================================================
// final_mma: out = P*X + bias. A = Phi/Plo copy, B = Xhi/Xlo via trans.
// grid (32,2,NB), 512 threads, pipelined.
// =============================================================================
__global__ __launch_bounds__(NT) void final_mma(const float* __restrict__ bias,
                                                float* __restrict__ out) {
    extern __shared__ __align__(16) char sm[];
    const u32 smb = smem_u32(sm);
    const int nt = blockIdx.x, mt = blockIdx.y, b = blockIdx.z;
    const int tid = threadIdx.x, lane = tid & 31, wid = tid >> 5;
    const int wm = wid >> 2, wn = wid & 3;
    const int g = lane >> 3, r8 = lane & 7;
    const int offA = (r8 + (g & 1) * 8) * LDW + (g >> 1) * 8;
    const int offBT = (r8 + (g & 1) * 8) * LDWB + (g >> 1) * 8;
    const int fr = tid >> 2, fs = (tid & 3) * 32;
    const int r2 = tid >> 3, f2 = (tid & 7) * 32;

    float acc[2][4][4] = {};
    const int NCH = 4;

#define FIN_FILL(st, c) do {                                                        \
    const int _k0 = (c) * 64;                                                       \
    const u32 _sb = smb + (st) * STG_T;                                             \
    const char* _ah = (const char*)&g_Phi[b][mt * 128 + fr][_k0] + fs;              \
    const char* _al = (const char*)&g_Plo[b][mt * 128 + fr][_k0] + fs;              \
    u32 _dA = _sb + fr * 144 + fs;                                                  \
    CP16(_dA, _ah); CP16(_dA + 16, _ah + 16);                                       \
    CP16(_dA + TA, _al); CP16(_dA + TA + 16, _al + 16);                             \
    const char* _bh = (const char*)&g_Xhi[b][_k0 + r2][nt * 128] + f2;              \
    const char* _bl = (const char*)&g_Xlo[b][_k0 + r2][nt * 128] + f2;              \
    u32 _dB = _sb + 2 * TA + r2 * 272 + f2;                                         \
    CP16(_dB, _bh); CP16(_dB + 16, _bh + 16);                                       \
    CP16(_dB + TTB, _bl); CP16(_dB + TTB + 16, _bl + 16);                           \
    CP_COMMIT();                                                                    \
} while (0)

    FIN_FILL(0, 0);
    for (int c = 0; c < NCH; c++) {
        const int st = c & 1;
        if (c + 1 < NCH) { FIN_FILL(st ^ 1, c + 1); CP_WAIT1(); }
        else CP_WAIT0();
        __syncthreads();
        const u32 aHb = smb + st * STG_T;
        mma_stage<true>(aHb, aHb + TA, aHb + 2 * TA, aHb + 2 * TA + TTB, offA, offBT, wm, wn, acc);
        __syncthreads();
    }

    const int coB = mt * 128 + wm * 32 + (lane >> 2);
    const int nsB = nt * 128 + wn * 32 + 2 * (lane & 3);
#pragma unroll
    for (int mf = 0; mf < 2; mf++) {
        int co = coB + mf * 16;
        float bv0 = bias[co], bv1 = bias[co + 8];
        float* row0 = out + ((size_t)b * NC + co) * NS;
        float* row1 = out + ((size_t)b * NC + co + 8) * NS;
#pragma unroll
        for (int nb = 0; nb < 4; nb++) {
            int cc = nsB + nb * 8;
            float2 v0; v0.x = acc[mf][nb][0] + bv0; v0.y = acc[mf][nb][1] + bv0;
            float2 v1; v1.x = acc[mf][nb][2] + bv1; v1.y = acc[mf][nb][3] + bv1;
            *(float2*)&row0[cc] = v0;
            *(float2*)&row1[cc] = v1;
        }
    }
}

// =============================================================================
extern "C" void kernel_launch(void* const* d_in, const int* in_sizes, int n_in,
                              void* d_out, int out_size) {
    (void)in_sizes; (void)n_in; (void)out_size;
    const float* x     = (const float*)d_in[0];
    const float* w_qkv = (const float*)d_in[1];
    const float* w_out = (const float*)d_in[2];
    const float* b_out = (const float*)d_in[3];
    float* out = (float*)d_out;

    cudaFuncSetAttribute(gram_mma, cudaFuncAttributeMaxDynamicSharedMemorySize, PIPE_A);
    cudaFuncSetAttribute(gemm_tc0, cudaFuncAttributeMaxDynamicSharedMemorySize, PIPE_A);
    cudaFuncSetAttribute(gemm_tc1, cudaFuncAttributeMaxDynamicSharedMemorySize, PIPE_T);
    cudaFuncSetAttribute(final_mma, cudaFuncAttributeMaxDynamicSharedMemorySize, PIPE_T);

    convert_x<<<NB * NC * NS / (256 * 8), 256>>>(x);
    convert_w<<<(NH * NC + NC * NH) / (256 * 8), 256>>>(w_qkv, w_out);
    gram_mma<<<dim3(3, KSPLIT, NB), NT, PIPE_A>>>();
    reduce_split_g<<<dim3(16, NB), 256>>>();
    gemm_tc0<<<dim3(2, 4, NB), NT, PIPE_A>>>();
    attn_kernel<<<dim3(NHEADS, 4, NB), 256>>>(w_qkv);
    gemm_tc1<<<dim3(2, 2, NB), NT, PIPE_T>>>();
    final_mma<<<dim3(32, 2, NB), NT, PIPE_T>>>(b_out, out);
}

// round 16
// speedup vs baseline: 1.1628x; 1.1628x over previous
#include <cuda_runtime.h>
#include <cuda_bf16.h>

#define NB 16
#define NC 256
#define NS 4096
#define NH 512
#define NHEADS 8
#define KSPLIT 3

typedef unsigned long long u64;
typedef unsigned int u32;
typedef unsigned short u16;

// ---------------- scratch (static device memory, 16B-aligned) ----------------
__device__ __align__(16) float g_Gpart[KSPLIT][NB][NC][NC];  // 12 MB
__device__ __align__(16) float g_QG[NB][NH][NC];             // 8 MB
__device__ __align__(16) __nv_bfloat16 g_Ghi[NB][NC][NC];    // 2 MB
__device__ __align__(16) __nv_bfloat16 g_Glo[NB][NC][NC];    // 2 MB
__device__ __align__(16) __nv_bfloat16 g_Mhi[NB][NH][NC];    // 4 MB
__device__ __align__(16) __nv_bfloat16 g_Mlo[NB][NH][NC];    // 4 MB
__device__ __align__(16) __nv_bfloat16 g_Phi[NB][NC][NC];    // 2 MB
__device__ __align__(16) __nv_bfloat16 g_Plo[NB][NC][NC];    // 2 MB
__device__ __align__(16) __nv_bfloat16 g_Xhi[NB][NC][NS];    // 32 MB
__device__ __align__(16) __nv_bfloat16 g_Xlo[NB][NC][NS];    // 32 MB
__device__ __align__(16) __nv_bfloat16 g_Wqhi[NH * NC], g_Wqlo[NH * NC];
__device__ __align__(16) __nv_bfloat16 g_Wouthi[NC * NH], g_Woutlo[NC * NH];

// ---------------- helpers ----------------------------------------------------
__device__ __forceinline__ u32 smem_u32(const void* p) {
    u32 a;
    asm("{ .reg .u64 t; cvta.to.shared.u64 t, %1; cvt.u32.u64 %0, t; }" : "=r"(a) : "l"(p));
    return a;
}
__device__ __forceinline__ void split4(float4 v, u64& hv, u64& lv) {
    __nv_bfloat16 h0 = __float2bfloat16(v.x), h1 = __float2bfloat16(v.y);
    __nv_bfloat16 h2 = __float2bfloat16(v.z), h3 = __float2bfloat16(v.w);
    __nv_bfloat16 l0 = __float2bfloat16(v.x - __bfloat162float(h0));
    __nv_bfloat16 l1 = __float2bfloat16(v.y - __bfloat162float(h1));
    __nv_bfloat16 l2 = __float2bfloat16(v.z - __bfloat162float(h2));
    __nv_bfloat16 l3 = __float2bfloat16(v.w - __bfloat162float(h3));
    hv = (u64)__bfloat16_as_ushort(h0) | ((u64)__bfloat16_as_ushort(h1) << 16) |
         ((u64)__bfloat16_as_ushort(h2) << 32) | ((u64)__bfloat16_as_ushort(h3) << 48);
    lv = (u64)__bfloat16_as_ushort(l0) | ((u64)__bfloat16_as_ushort(l1) << 16) |
         ((u64)__bfloat16_as_ushort(l2) << 32) | ((u64)__bfloat16_as_ushort(l3) << 48);
}
__device__ __forceinline__ void split1(float v, __nv_bfloat16& h, __nv_bfloat16& l) {
    h = __float2bfloat16(v);
    l = __float2bfloat16(v - __bfloat162float(h));
}
__device__ __forceinline__ void split2_u32(float a, float b, u32& hw, u32& lw) {
    __nv_bfloat16 ha, la, hb, lb;
    split1(a, ha, la);
    split1(b, hb, lb);
    hw = (u32)__bfloat16_as_ushort(ha) | ((u32)__bfloat16_as_ushort(hb) << 16);
    lw = (u32)__bfloat16_as_ushort(la) | ((u32)__bfloat16_as_ushort(lb) << 16);
}
__device__ __forceinline__ void ldsm4(u32* r, u32 addr) {
    asm volatile("ldmatrix.sync.aligned.m8n8.x4.shared.b16 {%0,%1,%2,%3}, [%4];"
                 : "=r"(r[0]), "=r"(r[1]), "=r"(r[2]), "=r"(r[3]) : "r"(addr));
}
__device__ __forceinline__ void ldsm4t(u32* r, u32 addr) {
    asm volatile("ldmatrix.sync.aligned.m8n8.x4.trans.shared.b16 {%0,%1,%2,%3}, [%4];"
                 : "=r"(r[0]), "=r"(r[1]), "=r"(r[2]), "=r"(r[3]) : "r"(addr));
}
__device__ __forceinline__ void mma_bf16(float* d, const u32* a, const u32* b) {
    asm volatile("mma.sync.aligned.m16n8k16.row.col.f32.bf16.bf16.f32 "
        "{%0,%1,%2,%3}, {%4,%5,%6,%7}, {%8,%9}, {%0,%1,%2,%3};"
        : "+f"(d[0]), "+f"(d[1]), "+f"(d[2]), "+f"(d[3])
        : "r"(a[0]), "r"(a[1]), "r"(a[2]), "r"(a[3]), "r"(b[0]), "r"(b[1]));
}
#define CP16(dst, src) asm volatile("cp.async.cg.shared.global [%0], [%1], 16;" :: "r"(dst), "l"(src))
#define CP_COMMIT()    asm volatile("cp.async.commit_group;" ::: "memory")
#define CP_WAIT1()     asm volatile("cp.async.wait_group 1;" ::: "memory")
#define CP_WAIT0()     asm volatile("cp.async.wait_group 0;" ::: "memory")

#define LDW 72
#define LDWB 136
#define TA 18432
#define TTB 17408
#define STG_A (4 * TA)
#define STG_T (2 * TA + 2 * TTB)
#define PIPE_A (2 * STG_A)
#define PIPE_T (2 * STG_T)
#define NT 512

// shared mma stage: A nontrans always; B nontrans (TB=0) or trans (TB=1)
template <bool TB>
__device__ __forceinline__ void mma_stage(u32 aHb, u32 aLb, u32 bHb, u32 bLb,
                                          int offA, int offBx, int wm, int wn,
                                          float acc[2][4][4]) {
#pragma unroll
    for (int ks = 0; ks < 4; ks++) {
        u32 ah[2][4], al[2][4], bh[2][4], bl[2][4];
#pragma unroll
        for (int mf = 0; mf < 2; mf++) {
            u32 o = 2u * (u32)(offA + (wm * 32 + mf * 16) * LDW + ks * 16);
            ldsm4(ah[mf], aHb + o);
            ldsm4(al[mf], aLb + o);
        }
#pragma unroll
        for (int p = 0; p < 2; p++) {
            if (TB) {
                u32 o = 2u * (u32)(offBx + ks * 16 * LDWB + wn * 32 + p * 16);
                ldsm4t(bh[p], bHb + o);
                ldsm4t(bl[p], bLb + o);
            } else {
                u32 o = 2u * (u32)(offBx + (wn * 32 + p * 16) * LDW + ks * 16);
                ldsm4(bh[p], bHb + o);
                ldsm4(bl[p], bLb + o);
            }
        }
#pragma unroll
        for (int mf = 0; mf < 2; mf++)
#pragma unroll
            for (int p = 0; p < 2; p++)
#pragma unroll
                for (int hh = 0; hh < 2; hh++) {
                    int nb = p * 2 + hh;
                    mma_bf16(acc[mf][nb], ah[mf], &bh[p][hh * 2]);
                    mma_bf16(acc[mf][nb], ah[mf], &bl[p][hh * 2]);
                    mma_bf16(acc[mf][nb], al[mf], &bh[p][hh * 2]);
                }
    }
}

// =============================================================================
// convert_x: X fp32 -> Xhi/Xlo bf16 [b][c][ns]. grid 8192 x 256.
// =============================================================================
__global__ __launch_bounds__(256) void convert_x(const float* __restrict__ x) {
    size_t i = ((size_t)blockIdx.x * 256 + threadIdx.x) * 8;
    float4 v0 = *(const float4*)(x + i);
    float4 v1 = *(const float4*)(x + i + 4);
    u64 h0, l0, h1, l1;
    split4(v0, h0, l0);
    split4(v1, h1, l1);
    *(ulonglong2*)((__nv_bfloat16*)g_Xhi + i) = make_ulonglong2(h0, h1);
    *(ulonglong2*)((__nv_bfloat16*)g_Xlo + i) = make_ulonglong2(l0, l1);
}

// =============================================================================
// convert_w: Wq + W_out -> split bf16. grid 128 x 256.
// =============================================================================
__global__ __launch_bounds__(256) void convert_w(const float* __restrict__ wq,
                                                 const float* __restrict__ wo) {
    int i = (blockIdx.x * 256 + threadIdx.x) * 8;
    const int NQ = NH * NC;
    const float* src;
    __nv_bfloat16 *dh, *dl;
    if (i < NQ) { src = wq + i; dh = g_Wqhi + i; dl = g_Wqlo + i; }
    else { int o = i - NQ; src = wo + o; dh = g_Wouthi + o; dl = g_Woutlo + o; }
    float4 v0 = *(const float4*)src;
    float4 v1 = *(const float4*)(src + 4);
    u64 h0, l0, h1, l1;
    split4(v0, h0, l0);
    split4(v1, h1, l1);
    *(ulonglong2*)dh = make_ulonglong2(h0, h1);
    *(ulonglong2*)dl = make_ulonglong2(l0, l1);
}

// =============================================================================
// gram_mma: symmetric blocks ((0,0),(0,1),(1,1)) x 3 k-splits (22/21/21 chunks).
// grid (3, KSPLIT, NB) = 144 CTAs (~1 balanced wave), 512 thr.
// =============================================================================
__global__ __launch_bounds__(NT) void gram_mma() {
    extern __shared__ __align__(16) char sm[];
    const u32 smb = smem_u32(sm);

    const int bx = blockIdx.x;
    const int bi = (bx == 2) ? 1 : 0;
    const int bj = (bx == 0) ? 0 : 1;
    const int s = blockIdx.y, b = blockIdx.z;
    const int tid = threadIdx.x, lane = tid & 31, wid = tid >> 5;
    const int wm = wid >> 2, wn = wid & 3;
    const bool diag = (bi == bj);

    const int g = lane >> 3, r8 = lane & 7;
    const int offA = (r8 + (g & 1) * 8) * LDW + (g >> 1) * 8;
    const int offB = (r8 + (g >> 1) * 8) * LDW + (g & 1) * 8;

    const int fr = tid >> 2, fs = (tid & 3) * 32;

    // 64 chunks split 22/21/21
    const int c0 = (s == 0) ? 0 : 22 + (s - 1) * 21;
    const int NCH = (s == 0) ? 22 : 21;

    float acc[2][4][4] = {};

#define GRAM_FILL(st, cAbs) do {                                                    \
    const int _k0 = (cAbs) * 64;                                                    \
    const u32 _sb = smb + (st) * STG_A;                                             \
    const char* _ah = (const char*)&g_Xhi[b][bi * 128 + fr][_k0] + fs;              \
    const char* _al = (const char*)&g_Xlo[b][bi * 128 + fr][_k0] + fs;              \
    u32 _dA = _sb + fr * 144 + fs;                                                  \
    CP16(_dA, _ah); CP16(_dA + 16, _ah + 16);                                       \
    CP16(_dA + TA, _al); CP16(_dA + TA + 16, _al + 16);                             \
    if (!diag) {                                                                    \
        const char* _bh = (const char*)&g_Xhi[b][bj * 128 + fr][_k0] + fs;          \
        const char* _bl = (const char*)&g_Xlo[b][bj * 128 + fr][_k0] + fs;          \
        u32 _dB = _sb + 2 * TA + fr * 144 + fs;                                     \
        CP16(_dB, _bh); CP16(_dB + 16, _bh + 16);                                   \
        CP16(_dB + TA, _bl); CP16(_dB + TA + 16, _bl + 16);                         \
    }                                                                               \
    CP_COMMIT();                                                                    \
} while (0)

    GRAM_FILL(0, c0);
    for (int c = 0; c < NCH; c++) {
        const int st = c & 1;
        if (c + 1 < NCH) { GRAM_FILL(st ^ 1, c0 + c + 1); CP_WAIT1(); }
        else CP_WAIT0();
        __syncthreads();
        const u32 aHb = smb + st * STG_A;
        const u32 aLb = aHb + TA;
        const u32 bHb = diag ? aHb : aHb + 2 * TA;
        const u32 bLb = diag ? aLb : aHb + 3 * TA;
        mma_stage<false>(aHb, aLb, bHb, bLb, offA, offB, wm, wn, acc);
        __syncthreads();
    }

    float* Gp = &g_Gpart[s][b][0][0];
    const int re = bi * 128 + wm * 32 + (lane >> 2);
    const int ce = bj * 128 + wn * 32 + 2 * (lane & 3);
#pragma unroll
    for (int mf = 0; mf < 2; mf++)
#pragma unroll
        for (int nb = 0; nb < 4; nb++) {
            int rr = re + mf * 16, cc = ce + nb * 8;
            float2 v0; v0.x = acc[mf][nb][0]; v0.y = acc[mf][nb][1];
            float2 v1; v1.x = acc[mf][nb][2]; v1.y = acc[mf][nb][3];
            *(float2*)&Gp[(size_t)rr * NC + cc] = v0;
            *(float2*)&Gp[(size_t)(rr + 8) * NC + cc] = v1;
        }
}

// =============================================================================
// reduce_split_g: G = sum_s Gpart[s], mirror block (1,0) from (0,1), split out.
// grid (16, NB), 256 thr.
// =============================================================================
__global__ __launch_bounds__(256) void reduce_split_g() {
    const int t = blockIdx.x, b = blockIdx.y;
    const int ti = t >> 2, tj = t & 3;
    const int tid = threadIdx.x;
    const int r = tid >> 2, j = tid & 3;
    const bool mirror = (ti >= 2 && tj < 2);
    const size_t ps = (size_t)NB * NC * NC;
    const float* P0 = &g_Gpart[0][b][0][0];

    if (!mirror) {
        int gr = ti * 64 + r, gc = tj * 64 + j * 16;
        u32 hw[8], lw[8];
#pragma unroll
        for (int q = 0; q < 4; q++) {
            float4 a = *(const float4*)(P0 + (size_t)gr * NC + gc + q * 4);
#pragma unroll
            for (int sp = 1; sp < KSPLIT; sp++) {
                float4 c = *(const float4*)(P0 + sp * ps + (size_t)gr * NC + gc + q * 4);
                a.x += c.x; a.y += c.y; a.z += c.z; a.w += c.w;
            }
            split2_u32(a.x, a.y, hw[2 * q], lw[2 * q]);
            split2_u32(a.z, a.w, hw[2 * q + 1], lw[2 * q + 1]);
        }
        uint4* dh = (uint4*)&g_Ghi[b][gr][gc];
        uint4* dl = (uint4*)&g_Glo[b][gr][gc];
        dh[0] = make_uint4(hw[0], hw[1], hw[2], hw[3]);
        dh[1] = make_uint4(hw[4], hw[5], hw[6], hw[7]);
        dl[0] = make_uint4(lw[0], lw[1], lw[2], lw[3]);
        dl[1] = make_uint4(lw[4], lw[5], lw[6], lw[7]);
    } else {
        __shared__ __align__(16) float T[64][68];
        int sr = tj * 64 + r, sc = ti * 64 + j * 16;
#pragma unroll
        for (int q = 0; q < 4; q++) {
            float4 a = *(const float4*)(P0 + (size_t)sr * NC + sc + q * 4);
#pragma unroll
            for (int sp = 1; sp < KSPLIT; sp++) {
                float4 c = *(const float4*)(P0 + sp * ps + (size_t)sr * NC + sc + q * 4);
                a.x += c.x; a.y += c.y; a.z += c.z; a.w += c.w;
            }
            *(float4*)&T[r][j * 16 + q * 4] = a;
        }
        __syncthreads();
        u32 hw[8], lw[8];
#pragma unroll
        for (int kk = 0; kk < 8; kk++)
            split2_u32(T[j * 16 + 2 * kk][r], T[j * 16 + 2 * kk + 1][r], hw[kk], lw[kk]);
        uint4* dh = (uint4*)&g_Ghi[b][ti * 64 + r][tj * 64 + j * 16];
        uint4* dl = (uint4*)&g_Glo[b][ti * 64 + r][tj * 64 + j * 16];
        dh[0] = make_uint4(hw[0], hw[1], hw[2], hw[3]);
        dh[1] = make_uint4(hw[4], hw[5], hw[6], hw[7]);
        dl[0] = make_uint4(lw[0], lw[1], lw[2], lw[3]);
        dl[1] = make_uint4(lw[4], lw[5], lw[6], lw[7]);
    }
}

// =============================================================================
// gemm_tc0: QG = Wq*G (K=256), all-copy fills, pipelined. grid (2,4,NB).
// =============================================================================
__global__ __launch_bounds__(NT) void gemm_tc0() {
    extern __shared__ __align__(16) char sm[];
    const u32 smb = smem_u32(sm);
    const int nt = blockIdx.x, mt = blockIdx.y, b = blockIdx.z;
    const int tid = threadIdx.x, lane = tid & 31, wid = tid >> 5;
    const int wm = wid >> 2, wn = wid & 3;
    const int g = lane >> 3, r8 = lane & 7;
    const int offA = (r8 + (g & 1) * 8) * LDW + (g >> 1) * 8;
    const int offB = (r8 + (g >> 1) * 8) * LDW + (g & 1) * 8;
    const int fr = tid >> 2, fs = (tid & 3) * 32;

    float acc[2][4][4] = {};
    const int NCH = 4;

#define TC0_FILL(st, c) do {                                                        \
    const int _k0 = (c) * 64;                                                       \
    const u32 _sb = smb + (st) * STG_A;                                             \
    const char* _ah = (const char*)(g_Wqhi + (size_t)(mt * 128 + fr) * NC + _k0) + fs; \
    const char* _al = (const char*)(g_Wqlo + (size_t)(mt * 128 + fr) * NC + _k0) + fs; \
    u32 _dA = _sb + fr * 144 + fs;                                                  \
    CP16(_dA, _ah); CP16(_dA + 16, _ah + 16);                                       \
    CP16(_dA + TA, _al); CP16(_dA + TA + 16, _al + 16);                             \
    const char* _bh = (const char*)&g_Ghi[b][nt * 128 + fr][_k0] + fs;              \
    const char* _bl = (const char*)&g_Glo[b][nt * 128 + fr][_k0] + fs;              \
    u32 _dB = _sb + 2 * TA + fr * 144 + fs;                                         \
    CP16(_dB, _bh); CP16(_dB + 16, _bh + 16);                                       \
    CP16(_dB + TA, _bl); CP16(_dB + TA + 16, _bl + 16);                             \
    CP_COMMIT();                                                                    \
} while (0)

    TC0_FILL(0, 0);
    for (int c = 0; c < NCH; c++) {
        const int st = c & 1;
        if (c + 1 < NCH) { TC0_FILL(st ^ 1, c + 1); CP_WAIT1(); }
        else CP_WAIT0();
        __syncthreads();
        const u32 aHb = smb + st * STG_A;
        mma_stage<false>(aHb, aHb + TA, aHb + 2 * TA, aHb + 3 * TA, offA, offB, wm, wn, acc);
        __syncthreads();
    }

    float* Cb = &g_QG[b][0][0];
    const int mB = mt * 128 + wm * 32 + (lane >> 2);
    const int nB = nt * 128 + wn * 32 + 2 * (lane & 3);
#pragma unroll
    for (int mf = 0; mf < 2; mf++) {
        int r = mB + mf * 16;
#pragma unroll
        for (int nb = 0; nb < 4; nb++) {
            int cc = nB + nb * 8;
            float2 v0; v0.x = acc[mf][nb][0]; v0.y = acc[mf][nb][1];
            float2 v1; v1.x = acc[mf][nb][2]; v1.y = acc[mf][nb][3];
            *(float2*)&Cb[(size_t)r * NC + cc] = v0;
            *(float2*)&Cb[(size_t)(r + 8) * NC + cc] = v1;
        }
    }
}

// =============================================================================
// gemm_tc1: P = W_out*M (K=512), B via trans, pipelined. grid (2,2,NB).
// =============================================================================
__global__ __launch_bounds__(NT) void gemm_tc1() {
    extern __shared__ __align__(16) char sm[];
    const u32 smb = smem_u32(sm);
    const int nt = blockIdx.x, mt = blockIdx.y, b = blockIdx.z;
    const int tid = threadIdx.x, lane = tid & 31, wid = tid >> 5;
    const int wm = wid >> 2, wn = wid & 3;
    const int g = lane >> 3, r8 = lane & 7;
    const int offA = (r8 + (g & 1) * 8) * LDW + (g >> 1) * 8;
    const int offBT = (r8 + (g & 1) * 8) * LDWB + (g >> 1) * 8;
    const int fr = tid >> 2, fs = (tid & 3) * 32;
    const int r2 = tid >> 3, f2 = (tid & 7) * 32;

    float acc[2][4][4] = {};
    const int NCH = 8;

#define TC1_FILL(st, c) do {                                                        \
    const int _k0 = (c) * 64;                                                       \
    const u32 _sb = smb + (st) * STG_T;                                             \
    const char* _ah = (const char*)(g_Wouthi + (size_t)(mt * 128 + fr) * NH + _k0) + fs; \
    const char* _al = (const char*)(g_Woutlo + (size_t)(mt * 128 + fr) * NH + _k0) + fs; \
    u32 _dA = _sb + fr * 144 + fs;                                                  \
    CP16(_dA, _ah); CP16(_dA + 16, _ah + 16);                                       \
    CP16(_dA + TA, _al); CP16(_dA + TA + 16, _al + 16);                             \
    const char* _bh = (const char*)&g_Mhi[b][_k0 + r2][nt * 128] + f2;              \
    const char* _bl = (const char*)&g_Mlo[b][_k0 + r2][nt * 128] + f2;              \
    u32 _dB = _sb + 2 * TA + r2 * 272 + f2;                                         \
    CP16(_dB, _bh); CP16(_dB + 16, _bh + 16);                                       \
    CP16(_dB + TTB, _bl); CP16(_dB + TTB + 16, _bl + 16);                           \
    CP_COMMIT();                                                                    \
} while (0)

    TC1_FILL(0, 0);
    for (int c = 0; c < NCH; c++) {
        const int st = c & 1;
        if (c + 1 < NCH) { TC1_FILL(st ^ 1, c + 1); CP_WAIT1(); }
        else CP_WAIT0();
        __syncthreads();
        const u32 aHb = smb + st * STG_T;
        mma_stage<true>(aHb, aHb + TA, aHb + 2 * TA, aHb + 2 * TA + TTB, offA, offBT, wm, wn, acc);
        __syncthreads();
    }

    const int mB = mt * 128 + wm * 32 + (lane >> 2);
    const int nB = nt * 128 + wn * 32 + 2 * (lane & 3);
#pragma unroll
    for (int mf = 0; mf < 2; mf++) {
        int r = mB + mf * 16;
#pragma unroll
        for (int nb = 0; nb < 4; nb++) {
            int cc = nB + nb * 8;
            u32 hw, lw;
            split2_u32(acc[mf][nb][0], acc[mf][nb][1], hw, lw);
            *(u32*)&g_Phi[b][r][cc] = hw;
            *(u32*)&g_Plo[b][r][cc] = lw;
            split2_u32(acc[mf][nb][2], acc[mf][nb][3], hw, lw);
            *(u32*)&g_Phi[b][r + 8][cc] = hw;
            *(u32*)&g_Plo[b][r + 8][cc] = lw;
        }
    }
}

// =============================================================================
// attn: sim -> softmax -> M = attn*Wv; writes M split bf16. grid (8,NB), 256t.
// =============================================================================
__global__ __launch_bounds__(256) void attn_kernel(const float* __restrict__ wqkv) {
    const int h = blockIdx.x, b = blockIdx.y;
    __shared__ float S[64][65];
    __shared__ __align__(16) float Buf[4160];
    const int tid = threadIdx.x, tx = tid & 15, ty = tid >> 4;

    const float* QGb = &g_QG[b][h * 64][0];
    const float* Wk = wqkv + (size_t)(NH + h * 64) * NC;
    const float* Wv = wqkv + (size_t)(2 * NH + h * 64) * NC;
    float* Qs = Buf;
    float* Ks = Buf + 64 * 32;

    float acc[4][4] = {};
    for (int kc = 0; kc < NC; kc += 32) {
#pragma unroll
        for (int it = 0; it < 2; it++) {
            int idx = it * 256 + tid;
            int row = idx >> 3, c4 = idx & 7;
            *(float4*)&Qs[row * 32 + c4 * 4] = *(const float4*)(QGb + (size_t)row * NC + kc + c4 * 4);
            float4 v = *(const float4*)(Wk + (size_t)row * NC + kc + c4 * 4);
            Ks[(c4 * 4 + 0) * 65 + row] = v.x;
            Ks[(c4 * 4 + 1) * 65 + row] = v.y;
            Ks[(c4 * 4 + 2) * 65 + row] = v.z;
            Ks[(c4 * 4 + 3) * 65 + row] = v.w;
        }
        __syncthreads();
#pragma unroll
        for (int kk = 0; kk < 32; kk++) {
            float a[4], bb[4];
#pragma unroll
            for (int i = 0; i < 4; i++) a[i] = Qs[(ty + 16 * i) * 32 + kk];
#pragma unroll
            for (int j = 0; j < 4; j++) bb[j] = Ks[kk * 65 + tx + 16 * j];
#pragma unroll
            for (int i = 0; i < 4; i++)
#pragma unroll
                for (int j = 0; j < 4; j++) acc[i][j] += a[i] * bb[j];
        }
        __syncthreads();
    }
    const float scale = 0.125f;
#pragma unroll
    for (int i = 0; i < 4; i++)
#pragma unroll
        for (int j = 0; j < 4; j++)
            S[ty + 16 * i][tx + 16 * j] = acc[i][j] * scale;
    __syncthreads();

    if (tid < 64) {
        float m = -1e30f;
        for (int j = 0; j < 64; j++) m = fmaxf(m, S[tid][j]);
        float sum = 0.f;
        for (int j = 0; j < 64; j++) {
            float e = expf(S[tid][j] - m);
            S[tid][j] = e; sum += e;
        }
        float inv = 1.f / sum;
        for (int j = 0; j < 64; j++) S[tid][j] *= inv;
    }
    __syncthreads();

    float* Vs = Buf;
    for (int cc = 0; cc < NC; cc += 64) {
#pragma unroll
        for (int it = 0; it < 4; it++) {
            int idx = it * 256 + tid;
            int row = idx >> 4, c4 = idx & 15;
            *(float4*)&Vs[row * 64 + c4 * 4] = *(const float4*)(Wv + (size_t)row * NC + cc + c4 * 4);
        }
        __syncthreads();
        float o[4][4] = {};
        for (int j = 0; j < 64; j++) {
            float a[4], vv[4];
#pragma unroll
            for (int i = 0; i < 4; i++) a[i] = S[ty + 16 * i][j];
#pragma unroll
            for (int jj = 0; jj < 4; jj++) vv[jj] = Vs[j * 64 + tx + 16 * jj];
#pragma unroll
            for (int i = 0; i < 4; i++)
#pragma unroll
                for (int jj = 0; jj < 4; jj++) o[i][jj] += a[i] * vv[jj];
        }
#pragma unroll
        for (int i = 0; i < 4; i++)
#pragma unroll
            for (int jj = 0; jj < 4; jj++) {
                __nv_bfloat16 hv, lv;
                split1(o[i][jj], hv, lv);
                int hd = h * 64 + ty + 16 * i, ccol = cc + tx + 16 * jj;
                g_Mhi[b][hd][ccol] = hv;
                g_Mlo[b][hd][ccol] = lv;
            }
        __syncthreads();
    }
}

// =============================================================================
// final_mma: out = P*X + bias. A = Phi/Plo copy, B = Xhi/Xlo via trans.
// grid (32,2,NB), 512 threads, pipelined.
// =============================================================================
__global__ __launch_bounds__(NT) void final_mma(const float* __restrict__ bias,
                                                float* __restrict__ out) {
    extern __shared__ __align__(16) char sm[];
    const u32 smb = smem_u32(sm);
    const int nt = blockIdx.x, mt = blockIdx.y, b = blockIdx.z;
    const int tid = threadIdx.x, lane = tid & 31, wid = tid >> 5;
    const int wm = wid >> 2, wn = wid & 3;
    const int g = lane >> 3, r8 = lane & 7;
    const int offA = (r8 + (g & 1) * 8) * LDW + (g >> 1) * 8;
    const int offBT = (r8 + (g & 1) * 8) * LDWB + (g >> 1) * 8;
    const int fr = tid >> 2, fs = (tid & 3) * 32;
    const int r2 = tid >> 3, f2 = (tid & 7) * 32;

    float acc[2][4][4] = {};
    const int NCH = 4;

#define FIN_FILL(st, c) do {                                                        \
    const int _k0 = (c) * 64;                                                       \
    const u32 _sb = smb + (st) * STG_T;                                             \
    const char* _ah = (const char*)&g_Phi[b][mt * 128 + fr][_k0] + fs;              \
    const char* _al = (const char*)&g_Plo[b][mt * 128 + fr][_k0] + fs;              \
    u32 _dA = _sb + fr * 144 + fs;                                                  \
    CP16(_dA, _ah); CP16(_dA + 16, _ah + 16);                                       \
    CP16(_dA + TA, _al); CP16(_dA + TA + 16, _al + 16);                             \
    const char* _bh = (const char*)&g_Xhi[b][_k0 + r2][nt * 128] + f2;              \
    const char* _bl = (const char*)&g_Xlo[b][_k0 + r2][nt * 128] + f2;              \
    u32 _dB = _sb + 2 * TA + r2 * 272 + f2;                                         \
    CP16(_dB, _bh); CP16(_dB + 16, _bh + 16);                                       \
    CP16(_dB + TTB, _bl); CP16(_dB + TTB + 16, _bl + 16);                           \
    CP_COMMIT();                                                                    \
} while (0)

    FIN_FILL(0, 0);
    for (int c = 0; c < NCH; c++) {
        const int st = c & 1;
        if (c + 1 < NCH) { FIN_FILL(st ^ 1, c + 1); CP_WAIT1(); }
        else CP_WAIT0();
        __syncthreads();
        const u32 aHb = smb + st * STG_T;
        mma_stage<true>(aHb, aHb + TA, aHb + 2 * TA, aHb + 2 * TA + TTB, offA, offBT, wm, wn, acc);
        __syncthreads();
    }

    const int coB = mt * 128 + wm * 32 + (lane >> 2);
    const int nsB = nt * 128 + wn * 32 + 2 * (lane & 3);
#pragma unroll
    for (int mf = 0; mf < 2; mf++) {
        int co = coB + mf * 16;
        float bv0 = bias[co], bv1 = bias[co + 8];
        float* row0 = out + ((size_t)b * NC + co) * NS;
        float* row1 = out + ((size_t)b * NC + co + 8) * NS;
#pragma unroll
        for (int nb = 0; nb < 4; nb++) {
            int cc = nsB + nb * 8;
            float2 v0; v0.x = acc[mf][nb][0] + bv0; v0.y = acc[mf][nb][1] + bv0;
            float2 v1; v1.x = acc[mf][nb][2] + bv1; v1.y = acc[mf][nb][3] + bv1;
            *(float2*)&row0[cc] = v0;
            *(float2*)&row1[cc] = v1;
        }
    }
}

// =============================================================================
extern "C" void kernel_launch(void* const* d_in, const int* in_sizes, int n_in,
                              void* d_out, int out_size) {
    (void)in_sizes; (void)n_in; (void)out_size;
    const float* x     = (const float*)d_in[0];
    const float* w_qkv = (const float*)d_in[1];
    const float* w_out = (const float*)d_in[2];
    const float* b_out = (const float*)d_in[3];
    float* out = (float*)d_out;

    cudaFuncSetAttribute(gram_mma, cudaFuncAttributeMaxDynamicSharedMemorySize, PIPE_A);
    cudaFuncSetAttribute(gemm_tc0, cudaFuncAttributeMaxDynamicSharedMemorySize, PIPE_A);
    cudaFuncSetAttribute(gemm_tc1, cudaFuncAttributeMaxDynamicSharedMemorySize, PIPE_T);
    cudaFuncSetAttribute(final_mma, cudaFuncAttributeMaxDynamicSharedMemorySize, PIPE_T);

    convert_x<<<NB * NC * NS / (256 * 8), 256>>>(x);
    convert_w<<<(NH * NC + NC * NH) / (256 * 8), 256>>>(w_qkv, w_out);
    gram_mma<<<dim3(3, KSPLIT, NB), NT, PIPE_A>>>();
    reduce_split_g<<<dim3(16, NB), 256>>>();
    gemm_tc0<<<dim3(2, 4, NB), NT, PIPE_A>>>();
    attn_kernel<<<dim3(NHEADS, NB), 256>>>(w_qkv);
    gemm_tc1<<<dim3(2, 2, NB), NT, PIPE_T>>>();
    final_mma<<<dim3(32, 2, NB), NT, PIPE_T>>>(b_out, out);
}